// round 2
// baseline (speedup 1.0000x reference)
#include <cuda_runtime.h>
#include <math.h>

#define BB 2
#define N1 384
#define N2 384
#define DD 128
#define HH 128
#define LL 3
#define NF 54

// ---------------- scratch (device globals; no allocation) ----------------
static __device__ float g_h1g[BB*N1*DD];
static __device__ float g_h2g[BB*N2*DD];
static __device__ float g_h  [BB*N1*DD];
static __device__ float g_hA [BB*N1*DD];
static __device__ float g_att[BB*N1*N1];
static __device__ float g_p1 [5*BB*N1*HH];
static __device__ float g_p2 [5*BB*N2*HH];
static __device__ float g_WA [LL*DD*DD];
static __device__ float g_bA [LL*DD];
static __device__ float g_pec[96];
static __device__ float g_pev[96];

__device__ __forceinline__ float sigmoidf_(float x){ return 1.f/(1.f+__expf(-x)); }

// ---------------- WA = W@A, bA = Wb@A (per layer) ----------------
__global__ __launch_bounds__(DD) void k_precompute(const float* __restrict__ W,
                                                   const float* __restrict__ Wb,
                                                   const float* __restrict__ A){
    int l = blockIdx.x / DD, k = blockIdx.x % DD, d = threadIdx.x;
    __shared__ float sw[DD];
    __shared__ float sb[DD];
    sw[d] = W[(l*DD + k)*DD + d];
    if (k == 0) sb[d] = Wb[l*DD + d];
    __syncthreads();
    const float* Al = A + l*DD*DD;
    float acc = 0.f;
    #pragma unroll 4
    for (int m = 0; m < DD; m++) acc += sw[m]*Al[m*DD + d];
    g_WA[(l*DD + k)*DD + d] = acc;
    if (k == 0){
        float bacc = 0.f;
        #pragma unroll 4
        for (int m = 0; m < DD; m++) bacc += sb[m]*Al[m*DD + d];
        g_bA[l*DD + d] = bacc;
    }
}

// ---------------- node projection: h1g=h1@nodeW, h2g=h2@nodeW (4 rows/block) ----------------
__global__ __launch_bounds__(DD) void k_node(const float* __restrict__ h1,
                                             const float* __restrict__ h2,
                                             const float* __restrict__ nW){
    int r0 = blockIdx.x*4, d = threadIdx.x;
    __shared__ float sx[4][NF];
    bool lig = (r0 < BB*N1);
    const float* src = lig ? (h1 + r0*NF) : (h2 + (r0 - BB*N1)*NF);
    for (int idx = d; idx < 4*NF; idx += DD) ((float*)sx)[idx] = src[idx];
    __syncthreads();
    float acc[4] = {0.f,0.f,0.f,0.f};
    #pragma unroll 2
    for (int k = 0; k < NF; k++){
        float wv = nW[k*DD + d];
        #pragma unroll
        for (int ii = 0; ii < 4; ii++) acc[ii] += sx[ii][k]*wv;
    }
    float* dst = lig ? (g_h1g + r0*DD) : (g_h2g + (r0 - BB*N1)*DD);
    #pragma unroll
    for (int ii = 0; ii < 4; ii++) dst[ii*DD + d] = acc[ii];
}

// ---------------- h = x@W+Wb ; hA = x@WA+bA (4 rows/block) ----------------
__global__ __launch_bounds__(DD) void k_gat_h(const float* __restrict__ gatW,
                                              const float* __restrict__ gatWb, int l){
    int b = blockIdx.x/(N1/4), i0 = (blockIdx.x % (N1/4))*4, d = threadIdx.x;
    __shared__ float sx[4][DD];
    #pragma unroll
    for (int ii = 0; ii < 4; ii++) sx[ii][d] = g_h1g[(b*N1 + i0 + ii)*DD + d];
    __syncthreads();
    const float* W  = gatW + l*DD*DD;
    const float* WA = g_WA + l*DD*DD;
    float wb  = gatWb[l*DD + d];
    float bav = g_bA [l*DD + d];
    float h[4], ha[4];
    #pragma unroll
    for (int ii = 0; ii < 4; ii++){ h[ii] = wb; ha[ii] = bav; }
    #pragma unroll 4
    for (int k = 0; k < DD; k++){
        float wv  = W [k*DD + d];
        float wav = WA[k*DD + d];
        #pragma unroll
        for (int ii = 0; ii < 4; ii++){
            h [ii] += sx[ii][k]*wv;
            ha[ii] += sx[ii][k]*wav;
        }
    }
    #pragma unroll
    for (int ii = 0; ii < 4; ii++){
        g_h [(b*N1 + i0 + ii)*DD + d] = h [ii];
        g_hA[(b*N1 + i0 + ii)*DD + d] = ha[ii];
    }
}

// ---------------- attention: e(j,k)=hA_j.h_k + hA_k.h_j, col-softmax, *adj (8 cols/block) ----------------
#define TC 8
__global__ __launch_bounds__(256) void k_att(const float* __restrict__ adj){
    int b  = blockIdx.x / (N1/TC);
    int c0 = (blockIdx.x % (N1/TC))*TC;
    __shared__ float s_hc [TC][DD];
    __shared__ float s_hac[TC][DD];
    __shared__ float s_e  [TC][N1+1];
    __shared__ float s_adj[TC][N1+1];
    int tid = threadIdx.x;
    for (int idx = tid; idx < TC*DD; idx += 256){
        int cc = idx/DD, d = idx%DD;
        s_hc [cc][d] = g_h [(b*N1 + c0 + cc)*DD + d];
        s_hac[cc][d] = g_hA[(b*N1 + c0 + cc)*DD + d];
    }
    __syncthreads();
    int w = tid >> 5, lane = tid & 31;
    for (int r = w; r < N1; r += 8){
        const float* hr  = g_h  + (b*N1 + r)*DD;
        const float* har = g_hA + (b*N1 + r)*DD;
        float acc[TC];
        #pragma unroll
        for (int cc = 0; cc < TC; cc++) acc[cc] = 0.f;
        #pragma unroll
        for (int t = 0; t < 4; t++){
            int d = lane + 32*t;
            float hv = hr[d], hav = har[d];
            #pragma unroll
            for (int cc = 0; cc < TC; cc++)
                acc[cc] += hav*s_hc[cc][d] + s_hac[cc][d]*hv;
        }
        #pragma unroll
        for (int o = 16; o; o >>= 1)
            #pragma unroll
            for (int cc = 0; cc < TC; cc++)
                acc[cc] += __shfl_xor_sync(0xffffffffu, acc[cc], o);
        if (lane < TC){
            int cc = lane;
            float a = adj[(b*N1 + r)*N1 + c0 + cc];
            s_adj[cc][r] = a;
            s_e  [cc][r] = (a > 0.f) ? acc[cc] : -9e15f;
        }
    }
    __syncthreads();
    // warp w owns column w: softmax over rows
    {
        int cc = w;
        float mx = -INFINITY;
        for (int r = lane; r < N1; r += 32) mx = fmaxf(mx, s_e[cc][r]);
        #pragma unroll
        for (int o = 16; o; o >>= 1) mx = fmaxf(mx, __shfl_xor_sync(0xffffffffu, mx, o));
        float sum = 0.f;
        for (int r = lane; r < N1; r += 32){
            float e = __expf(s_e[cc][r] - mx);
            s_e[cc][r] = e; sum += e;
        }
        #pragma unroll
        for (int o = 16; o; o >>= 1) sum += __shfl_xor_sync(0xffffffffu, sum, o);
        float inv = 1.f/sum;
        for (int r = lane; r < N1; r += 32)
            g_att[(b*N1 + r)*N1 + c0 + cc] = s_e[cc][r]*inv*s_adj[cc][r];
    }
}

// ---------------- h' = relu(att@h), gated residual into h1g (4 rows/block) ----------------
#define RI 4
__global__ __launch_bounds__(DD) void k_hprime(const float* __restrict__ gW,
                                               const float* __restrict__ gb, int l){
    int b  = blockIdx.x/(N1/RI);
    int i0 = (blockIdx.x % (N1/RI))*RI;
    int d  = threadIdx.x;
    __shared__ float s_att[RI][N1];
    __shared__ float s_red[DD];
    for (int idx = d; idx < RI*N1; idx += DD){
        int ii = idx/N1, j = idx%N1;
        s_att[ii][j] = g_att[(b*N1 + i0 + ii)*N1 + j];
    }
    __syncthreads();
    float hp[RI] = {0.f,0.f,0.f,0.f};
    const float* hb = g_h + (b*N1)*DD + d;
    #pragma unroll 4
    for (int j = 0; j < N1; j++){
        float hv = hb[j*DD];
        #pragma unroll
        for (int ii = 0; ii < RI; ii++) hp[ii] += s_att[ii][j]*hv;
    }
    float gw1 = gW[l*2*DD + d], gw2 = gW[l*2*DD + DD + d], gbv = gb[l];
    #pragma unroll
    for (int ii = 0; ii < RI; ii++){
        hp[ii] = fmaxf(hp[ii], 0.f);
        float xd = g_h1g[(b*N1 + i0 + ii)*DD + d];
        s_red[d] = xd*gw1 + hp[ii]*gw2;
        __syncthreads();
        for (int s = 64; s; s >>= 1){ if (d < s) s_red[d] += s_red[d + s]; __syncthreads(); }
        float g = s_red[0] + gbv;
        __syncthreads();
        float coeff = sigmoidf_(g);
        g_h1g[(b*N1 + i0 + ii)*DD + d] = coeff*xd + (1.f - coeff)*hp[ii];
    }
}

// ---------------- pair projections: p1=h1g@W1[:D]+b1, p2=h2g@W1[D:] (8 rows/block) ----------------
__global__ __launch_bounds__(HH) void k_pairproj(const float* __restrict__ W1,
                                                 const float* __restrict__ b1){
    int r0 = blockIdx.x*8, m = blockIdx.y, hh = threadIdx.x;
    __shared__ float sx[8][DD];
    bool lig = (r0 < BB*N1);
    const float* src = lig ? (g_h1g + r0*DD) : (g_h2g + (r0 - BB*N1)*DD);
    #pragma unroll
    for (int ii = 0; ii < 8; ii++) sx[ii][hh] = src[ii*DD + hh];
    __syncthreads();
    const float* W = W1 + m*2*DD*HH + (lig ? 0 : DD*HH);
    float bias = lig ? b1[m*HH + hh] : 0.f;
    float acc[8];
    #pragma unroll
    for (int ii = 0; ii < 8; ii++) acc[ii] = bias;
    #pragma unroll 4
    for (int k = 0; k < DD; k++){
        float wv = W[k*HH + hh];
        #pragma unroll
        for (int ii = 0; ii < 8; ii++) acc[ii] += sx[ii][k]*wv;
    }
    float* dst = lig ? (g_p1 + (m*BB*N1 + r0)*HH) : (g_p2 + (m*BB*N2 + (r0 - BB*N1))*HH);
    #pragma unroll
    for (int ii = 0; ii < 8; ii++) dst[ii*HH + hh] = acc[ii];
}

// ---------------- pair energies: 8 ligand rows/block, warp-per-j ----------------
#define TI 8
__global__ __launch_bounds__(256) void k_pair(const float* __restrict__ dmv,
                                              const float* __restrict__ c1,
                                              const float* __restrict__ c2,
                                              const float* __restrict__ eps,
                                              const float* __restrict__ sig,
                                              const float* __restrict__ val1,
                                              const float* __restrict__ val2,
                                              const float* __restrict__ nmm1,
                                              const float* __restrict__ nmm2,
                                              const float* __restrict__ W2,
                                              const float* __restrict__ b2,
                                              const float* __restrict__ vdwc){
    int blk = blockIdx.x;
    int b   = blk / (N1/TI);
    int i0  = (blk % (N1/TI))*TI;
    __shared__ float s_p1[5][TI][HH];
    __shared__ float s_w2[5][HH];
    __shared__ float s_b2[5];
    __shared__ float s_c1[TI], s_v1[TI], s_n1[TI];
    __shared__ float s_red[16];
    int tid = threadIdx.x;
    for (int idx = tid; idx < 5*TI*HH; idx += 256){
        int m = idx/(TI*HH), rem = idx%(TI*HH), ii = rem/HH, hh = rem%HH;
        s_p1[m][ii][hh] = g_p1[(m*BB*N1 + b*N1 + i0 + ii)*HH + hh];
    }
    for (int idx = tid; idx < 5*HH; idx += 256) s_w2[idx/HH][idx%HH] = W2[idx];
    if (tid < 5) s_b2[tid] = b2[tid];
    if (tid < TI){
        s_c1[tid] = c1[b*N1 + i0 + tid];
        s_v1[tid] = val1[b*N1 + i0 + tid];
        s_n1[tid] = nmm1[b*N1 + i0 + tid];
    }
    __syncthreads();
    float vdwc2 = vdwc[0]*vdwc[0];
    int w = tid >> 5, lane = tid & 31;
    float ec = 0.f, ev = 0.f;
    for (int j = w; j < N2; j += 8){
        float part[TI][5];
        #pragma unroll
        for (int ii = 0; ii < TI; ii++)
            #pragma unroll
            for (int m = 0; m < 5; m++) part[ii][m] = 0.f;
        #pragma unroll
        for (int t = 0; t < 4; t++){
            int hh = lane + 32*t;
            #pragma unroll
            for (int m = 0; m < 5; m++){
                float pv = g_p2[(m*BB*N2 + b*N2 + j)*HH + hh];
                float ww = s_w2[m][hh];
                #pragma unroll
                for (int ii = 0; ii < TI; ii++){
                    float s = s_p1[m][ii][hh] + pv;
                    part[ii][m] = fmaf(fmaxf(s, 0.f), ww, part[ii][m]);
                }
            }
        }
        #pragma unroll
        for (int o = 16; o; o >>= 1)
            #pragma unroll
            for (int ii = 0; ii < TI; ii++)
                #pragma unroll
                for (int m = 0; m < 5; m++)
                    part[ii][m] += __shfl_xor_sync(0xffffffffu, part[ii][m], o);
        if (lane < TI){
            int ii = lane;
            float v0 = part[ii][0] + s_b2[0];
            float v1 = part[ii][1] + s_b2[1];
            float v2 = part[ii][2] + s_b2[2];
            float v3 = part[ii][3] + s_b2[3];
            float v4 = part[ii][4] + s_b2[4];
            int pix = (b*N1 + i0 + ii)*N2 + j;
            const float* dv = dmv + (size_t)pix*3;
            float dx = dv[0], dy = dv[1], dz = dv[2];
            float dm = sqrtf(dx*dx + dy*dy + dz*dz + 1e-10f);
            if (dm < 0.5f) dm = 1e10f;
            float l2dm = __log2f(dm);
            // coulomb
            float cA  = sigmoidf_(v0);
            float cN  = 2.f*sigmoidf_(v1) + 1.f;
            float q12 = s_c1[ii]*c2[b*N2 + j];
            float e_c = cA*q12*exp2f(-cN*l2dm);
            e_c *= s_v1[ii]*val2[b*N2 + j];
            e_c = fminf(fmaxf(e_c, -100.f), 100.f);
            // vdw
            float vAv = (0.6f*sigmoidf_(v2) + 0.7f)*vdwc2*eps[pix];
            float vBv = tanhf(v3)*0.6f + 0.7f;
            float vNv = 2.f*sigmoidf_(v4) + 5.f;
            float dm0 = sig[pix]*vBv;
            if (dm0 < 1e-4f) dm0 = 1.f;
            float r  = exp2f(vNv*(__log2f(dm0) - l2dm));
            float e_v = vAv*(r*r - 2.f*r);
            e_v *= s_n1[ii]*nmm2[b*N2 + j];
            e_v = fminf(e_v, 100.f);
            ec += e_c; ev += e_v;
        }
    }
    #pragma unroll
    for (int o = 16; o; o >>= 1){
        ec += __shfl_xor_sync(0xffffffffu, ec, o);
        ev += __shfl_xor_sync(0xffffffffu, ev, o);
    }
    if (lane == 0){ s_red[w] = ec; s_red[8 + w] = ev; }
    __syncthreads();
    if (tid == 0){
        float tec = 0.f, tev = 0.f;
        #pragma unroll
        for (int q = 0; q < 8; q++){ tec += s_red[q]; tev += s_red[8 + q]; }
        g_pec[blk] = tec;
        g_pev[blk] = tev;
    }
}

// ---------------- finalize: intercept MLP + deterministic sums + e_u ----------------
__global__ __launch_bounds__(DD) void k_final(const float* __restrict__ valid1,
                                              const float* __restrict__ delta_uff,
                                              const float* __restrict__ duff,
                                              const float* __restrict__ iW1,
                                              const float* __restrict__ ib1,
                                              const float* __restrict__ iW2,
                                              const float* __restrict__ ib2,
                                              float* __restrict__ out){
    int b = blockIdx.x, d = threadIdx.x;
    __shared__ float s_hs[DD];
    __shared__ float s_red[DD];
    float hs = 0.f;
    for (int i = 0; i < N1; i++) hs += g_h1g[(b*N1 + i)*DD + d]*valid1[b*N1 + i];
    s_hs[d] = hs;
    __syncthreads();
    float hid = ib1[d];
    #pragma unroll 4
    for (int k = 0; k < DD; k++) hid += s_hs[k]*iW1[k*HH + d];
    hid = fmaxf(hid, 0.f);
    s_red[d] = hid*iW2[d];
    __syncthreads();
    for (int s = 64; s; s >>= 1){ if (d < s) s_red[d] += s_red[d + s]; __syncthreads(); }
    if (d == 0){
        float inter = s_red[0] + ib2[0];
        float tec = 0.f, tev = 0.f;
        const int nbb = N1/TI;           // 48 blocks per batch
        for (int q = 0; q < nbb; q++){ tec += g_pec[b*nbb + q]; tev += g_pev[b*nbb + q]; }
        out[b*4 + 0] = tec;
        out[b*4 + 1] = tev;
        out[b*4 + 2] = duff[0]*duff[0]*delta_uff[b];
        out[b*4 + 3] = inter;
    }
}

// ---------------- launch ----------------
// NOTE: d_in follows setup_inputs() dict insertion order:
//   0:h1  1:h2  2:adj1  3:dmv  4:charge1  5:charge2  6:vdw_epsilon  7:vdw_sigma
//   8:delta_uff  9:valid1  10:valid2  11:no_metal1  12:no_metal2  13:node_W
//   14:gat_W  15:gat_Wb  16:gat_A  17:gat_gW  18:gat_gb  19:pair_W1  20:pair_b1
//   21:pair_W2  22:pair_b2  23:vdw_coeff  24:duff_coeff  25:int_W1  26:int_b1
//   27:int_W2  28:int_b2
extern "C" void kernel_launch(void* const* d_in, const int* in_sizes, int n_in,
                              void* d_out, int out_size){
    const float* h1        = (const float*)d_in[0];
    const float* h2        = (const float*)d_in[1];
    const float* adj1      = (const float*)d_in[2];
    const float* dmv       = (const float*)d_in[3];
    const float* charge1   = (const float*)d_in[4];
    const float* charge2   = (const float*)d_in[5];
    const float* eps       = (const float*)d_in[6];
    const float* sig       = (const float*)d_in[7];
    const float* delta_uff = (const float*)d_in[8];
    const float* valid1    = (const float*)d_in[9];
    const float* valid2    = (const float*)d_in[10];
    const float* nm1       = (const float*)d_in[11];
    const float* nm2       = (const float*)d_in[12];
    const float* nodeW     = (const float*)d_in[13];
    const float* gatW      = (const float*)d_in[14];
    const float* gatWb     = (const float*)d_in[15];
    const float* gatA      = (const float*)d_in[16];
    const float* gatgW     = (const float*)d_in[17];
    const float* gatgb     = (const float*)d_in[18];
    const float* pW1       = (const float*)d_in[19];
    const float* pb1       = (const float*)d_in[20];
    const float* pW2       = (const float*)d_in[21];
    const float* pb2       = (const float*)d_in[22];
    const float* vdwc      = (const float*)d_in[23];
    const float* duffc     = (const float*)d_in[24];
    const float* iW1       = (const float*)d_in[25];
    const float* ib1       = (const float*)d_in[26];
    const float* iW2       = (const float*)d_in[27];
    const float* ib2       = (const float*)d_in[28];
    float* out = (float*)d_out;

    k_precompute<<<LL*DD, DD>>>(gatW, gatWb, gatA);
    k_node<<<(BB*(N1 + N2))/4, DD>>>(h1, h2, nodeW);
    for (int l = 0; l < LL; l++){
        k_gat_h <<<BB*N1/4,  DD >>>(gatW, gatWb, l);
        k_att   <<<BB*N1/TC, 256>>>(adj1);
        k_hprime<<<BB*N1/RI, DD >>>(gatgW, gatgb, l);
    }
    {
        dim3 gp((BB*(N1 + N2))/8, 5);
        k_pairproj<<<gp, HH>>>(pW1, pb1);
    }
    k_pair<<<BB*N1/TI, 256>>>(dmv, charge1, charge2, eps, sig,
                              valid1, valid2, nm1, nm2, pW2, pb2, vdwc);
    k_final<<<BB, DD>>>(valid1, delta_uff, duffc, iW1, ib1, iW2, ib2, out);
}

// round 3
// speedup vs baseline: 1.5438x; 1.5438x over previous
#include <cuda_runtime.h>
#include <math.h>

#define BB 2
#define N1 384
#define N2 384
#define DD 128
#define HH 128
#define LL 3
#define NF 54

// ---------------- scratch (device globals; no allocation) ----------------
static __device__ float g_h1g[BB*N1*DD];
static __device__ float g_h2g[BB*N2*DD];
static __device__ float g_h  [BB*N1*DD];
static __device__ float g_hA [BB*N1*DD];
static __device__ float g_P  [BB*N1*N1];
static __device__ float g_att[BB*N1*N1];
static __device__ float g_p1 [5*BB*N1*HH];
static __device__ float g_p2 [5*BB*N2*HH];
static __device__ float g_WA [LL*DD*DD];
static __device__ float g_bA [LL*DD];
static __device__ float g_pec[576];
static __device__ float g_pev[576];

__device__ __forceinline__ float sigmoidf_(float x){ return 1.f/(1.f+__expf(-x)); }

// ---------------- WA = W@A, bA = Wb@A (per layer) ----------------
__global__ __launch_bounds__(DD) void k_precompute(const float* __restrict__ W,
                                                   const float* __restrict__ Wb,
                                                   const float* __restrict__ A){
    int l = blockIdx.x / DD, k = blockIdx.x % DD, d = threadIdx.x;
    __shared__ float sw[DD];
    __shared__ float sb[DD];
    sw[d] = W[(l*DD + k)*DD + d];
    if (k == 0) sb[d] = Wb[l*DD + d];
    __syncthreads();
    const float* Al = A + l*DD*DD;
    float acc = 0.f;
    #pragma unroll 4
    for (int m = 0; m < DD; m++) acc += sw[m]*Al[m*DD + d];
    g_WA[(l*DD + k)*DD + d] = acc;
    if (k == 0){
        float bacc = 0.f;
        #pragma unroll 4
        for (int m = 0; m < DD; m++) bacc += sb[m]*Al[m*DD + d];
        g_bA[l*DD + d] = bacc;
    }
}

// ---------------- node projection: 4 rows/block ----------------
__global__ __launch_bounds__(DD) void k_node(const float* __restrict__ h1,
                                             const float* __restrict__ h2,
                                             const float* __restrict__ nW){
    int r0 = blockIdx.x*4, d = threadIdx.x;
    __shared__ float sx[4][NF];
    bool lig = (r0 < BB*N1);
    const float* src = lig ? (h1 + r0*NF) : (h2 + (r0 - BB*N1)*NF);
    for (int idx = d; idx < 4*NF; idx += DD) ((float*)sx)[idx] = src[idx];
    __syncthreads();
    float acc[4] = {0.f,0.f,0.f,0.f};
    #pragma unroll 2
    for (int k = 0; k < NF; k++){
        float wv = nW[k*DD + d];
        #pragma unroll
        for (int ii = 0; ii < 4; ii++) acc[ii] += sx[ii][k]*wv;
    }
    float* dst = lig ? (g_h1g + r0*DD) : (g_h2g + (r0 - BB*N1)*DD);
    #pragma unroll
    for (int ii = 0; ii < 4; ii++) dst[ii*DD + d] = acc[ii];
}

// ---------------- h = x@W+Wb ; hA = x@WA+bA (16 rows/block) ----------------
__global__ __launch_bounds__(DD) void k_gat_h(const float* __restrict__ gatW,
                                              const float* __restrict__ gatWb, int l){
    int r0 = blockIdx.x*16, d = threadIdx.x;
    __shared__ float sx[16][DD];
    #pragma unroll
    for (int ii = 0; ii < 16; ii++) sx[ii][d] = g_h1g[(r0 + ii)*DD + d];
    __syncthreads();
    const float* W  = gatW + l*DD*DD;
    const float* WA = g_WA + l*DD*DD;
    float wb  = gatWb[l*DD + d];
    float bav = g_bA [l*DD + d];
    float h[16], ha[16];
    #pragma unroll
    for (int ii = 0; ii < 16; ii++){ h[ii] = wb; ha[ii] = bav; }
    #pragma unroll 2
    for (int k = 0; k < DD; k++){
        float wv  = W [k*DD + d];
        float wav = WA[k*DD + d];
        #pragma unroll
        for (int ii = 0; ii < 16; ii++){
            h [ii] += sx[ii][k]*wv;
            ha[ii] += sx[ii][k]*wav;
        }
    }
    #pragma unroll
    for (int ii = 0; ii < 16; ii++){
        g_h [(r0 + ii)*DD + d] = h [ii];
        g_hA[(r0 + ii)*DD + d] = ha[ii];
    }
}

// ---------------- P = hA @ h^T : 64x64 tile register GEMM ----------------
#define ET 64
__global__ __launch_bounds__(256) void k_e(){
    int b  = blockIdx.z;
    int j0 = blockIdx.y*ET;
    int k0 = blockIdx.x*ET;
    __shared__ float sA[64][ET+4];   // [kk][row j]
    __shared__ float sB[64][ET+4];   // [kk][row k]
    int tid = threadIdx.x;
    int tx = tid & 15, ty = tid >> 4;
    float acc[4][4];
    #pragma unroll
    for (int r = 0; r < 4; r++)
        #pragma unroll
        for (int c = 0; c < 4; c++) acc[r][c] = 0.f;
    const float* baseA = g_hA + (b*N1 + j0)*DD;
    const float* baseB = g_h  + (b*N1 + k0)*DD;
    for (int ks = 0; ks < 2; ks++){
        __syncthreads();
        #pragma unroll
        for (int q = 0; q < 4; q++){
            int idx = tid + q*256;
            int row = idx >> 4;
            int kq  = idx & 15;
            float4 va = *(const float4*)(baseA + row*DD + ks*64 + kq*4);
            sA[kq*4+0][row] = va.x; sA[kq*4+1][row] = va.y;
            sA[kq*4+2][row] = va.z; sA[kq*4+3][row] = va.w;
            float4 vb = *(const float4*)(baseB + row*DD + ks*64 + kq*4);
            sB[kq*4+0][row] = vb.x; sB[kq*4+1][row] = vb.y;
            sB[kq*4+2][row] = vb.z; sB[kq*4+3][row] = vb.w;
        }
        __syncthreads();
        #pragma unroll 8
        for (int kk = 0; kk < 64; kk++){
            float4 av = *(const float4*)&sA[kk][ty*4];
            float4 bv = *(const float4*)&sB[kk][tx*4];
            float ar[4] = {av.x, av.y, av.z, av.w};
            float br[4] = {bv.x, bv.y, bv.z, bv.w};
            #pragma unroll
            for (int r = 0; r < 4; r++)
                #pragma unroll
                for (int c = 0; c < 4; c++)
                    acc[r][c] = fmaf(ar[r], br[c], acc[r][c]);
        }
    }
    #pragma unroll
    for (int r = 0; r < 4; r++){
        float4 o = make_float4(acc[r][0], acc[r][1], acc[r][2], acc[r][3]);
        *(float4*)&g_P[(b*N1 + j0 + ty*4 + r)*N1 + k0 + tx*4] = o;
    }
}

// ---------------- column softmax of e = P + P^T, masked by adj ----------------
// dynamic smem: sCol[384][33] + sRow[32][385]
#define SOFT_SMEM ((N1*33 + 32*385)*4)
__global__ __launch_bounds__(256) void k_soft(const float* __restrict__ adj){
    extern __shared__ float sm[];
    float* sCol = sm;                // [384][33]
    float* sRow = sm + N1*33;        // [32][385]
    int b  = blockIdx.y;
    int c0 = blockIdx.x*32;
    int tid = threadIdx.x;
    for (int idx = tid; idx < N1*32; idx += 256){
        int r = idx >> 5, c = idx & 31;
        float p = g_P[(b*N1 + r)*N1 + c0 + c];
        float a = adj[(b*N1 + r)*N1 + c0 + c];
        sCol[r*33 + c] = (a > 0.f) ? p : -9e15f;
    }
    for (int idx = tid; idx < 32*N1; idx += 256){
        int cc = idx / N1, r = idx % N1;
        sRow[cc*385 + r] = g_P[(b*N1 + c0 + cc)*N1 + r];
    }
    __syncthreads();
    int w = tid >> 5, lane = tid & 31;
    for (int cc = w; cc < 32; cc += 8){
        float ev[12];
        float mx = -INFINITY;
        #pragma unroll
        for (int t = 0; t < 12; t++){
            int r = lane + t*32;
            float e = sCol[r*33 + cc];
            if (e > -8e15f) e += sRow[cc*385 + r];
            ev[t] = e;
            mx = fmaxf(mx, e);
        }
        #pragma unroll
        for (int o = 16; o; o >>= 1) mx = fmaxf(mx, __shfl_xor_sync(0xffffffffu, mx, o));
        float sum = 0.f;
        #pragma unroll
        for (int t = 0; t < 12; t++){
            float x = __expf(ev[t] - mx);
            ev[t] = x; sum += x;
        }
        #pragma unroll
        for (int o = 16; o; o >>= 1) sum += __shfl_xor_sync(0xffffffffu, sum, o);
        float inv = 1.f/sum;
        #pragma unroll
        for (int t = 0; t < 12; t++) sCol[(lane + t*32)*33 + cc] = ev[t]*inv;
    }
    __syncthreads();
    for (int idx = tid; idx < N1*32; idx += 256){
        int r = idx >> 5, c = idx & 31;
        float a = adj[(b*N1 + r)*N1 + c0 + c];
        g_att[(b*N1 + r)*N1 + c0 + c] = sCol[r*33 + c]*a;
    }
}

// ---------------- h' = relu(att@h), gated residual into h1g (16 rows/block) ----------------
__global__ __launch_bounds__(DD) void k_hprime(const float* __restrict__ gW,
                                               const float* __restrict__ gb, int l){
    int r0 = blockIdx.x*16;
    int b  = r0 / N1;
    int d  = threadIdx.x;
    __shared__ float s_att[16][N1];
    __shared__ float s_g[16][DD];
    __shared__ float s_c[16];
    for (int idx = d; idx < 16*N1; idx += DD){
        int ii = idx / N1, j = idx % N1;
        s_att[ii][j] = g_att[(r0 + ii)*N1 + j];
    }
    float xd[16];
    #pragma unroll
    for (int ii = 0; ii < 16; ii++) xd[ii] = g_h1g[(r0 + ii)*DD + d];
    __syncthreads();
    float hp[16];
    #pragma unroll
    for (int ii = 0; ii < 16; ii++) hp[ii] = 0.f;
    const float* hb = g_h + (b*N1)*DD + d;
    #pragma unroll 4
    for (int j = 0; j < N1; j++){
        float hv = hb[j*DD];
        #pragma unroll
        for (int ii = 0; ii < 16; ii++) hp[ii] = fmaf(s_att[ii][j], hv, hp[ii]);
    }
    float gw1 = gW[l*2*DD + d], gw2 = gW[l*2*DD + DD + d], gbv = gb[l];
    #pragma unroll
    for (int ii = 0; ii < 16; ii++){
        hp[ii] = fmaxf(hp[ii], 0.f);
        s_g[ii][d] = fmaf(xd[ii], gw1, hp[ii]*gw2);
    }
    __syncthreads();
    int w = d >> 5, lane = d & 31;
    for (int ii = w; ii < 16; ii += 4){
        float s = s_g[ii][lane] + s_g[ii][lane+32] + s_g[ii][lane+64] + s_g[ii][lane+96];
        #pragma unroll
        for (int o = 16; o; o >>= 1) s += __shfl_xor_sync(0xffffffffu, s, o);
        if (lane == 0) s_c[ii] = sigmoidf_(s + gbv);
    }
    __syncthreads();
    #pragma unroll
    for (int ii = 0; ii < 16; ii++){
        float coeff = s_c[ii];
        g_h1g[(r0 + ii)*DD + d] = coeff*xd[ii] + (1.f - coeff)*hp[ii];
    }
}

// ---------------- pair projections (16 rows/block) ----------------
__global__ __launch_bounds__(HH) void k_pairproj(const float* __restrict__ W1,
                                                 const float* __restrict__ b1){
    int r0 = blockIdx.x*16, m = blockIdx.y, hh = threadIdx.x;
    __shared__ float sx[16][DD];
    bool lig = (r0 < BB*N1);
    const float* src = lig ? (g_h1g + r0*DD) : (g_h2g + (r0 - BB*N1)*DD);
    #pragma unroll
    for (int ii = 0; ii < 16; ii++) sx[ii][hh] = src[ii*DD + hh];
    __syncthreads();
    const float* W = W1 + m*2*DD*HH + (lig ? 0 : DD*HH);
    float bias = lig ? b1[m*HH + hh] : 0.f;
    float acc[16];
    #pragma unroll
    for (int ii = 0; ii < 16; ii++) acc[ii] = bias;
    #pragma unroll 2
    for (int k = 0; k < DD; k++){
        float wv = W[k*HH + hh];
        #pragma unroll
        for (int ii = 0; ii < 16; ii++) acc[ii] = fmaf(sx[ii][k], wv, acc[ii]);
    }
    float* dst = lig ? (g_p1 + (m*BB*N1 + r0)*HH) : (g_p2 + (m*BB*N2 + (r0 - BB*N1))*HH);
    #pragma unroll
    for (int ii = 0; ii < 16; ii++) dst[ii*HH + hh] = acc[ii];
}

// ---------------- pair energies: 16i x 32j tile, thread owns 2i x 1j ----------------
__global__ __launch_bounds__(256) void k_pair(const float* __restrict__ dmv,
                                              const float* __restrict__ c1,
                                              const float* __restrict__ c2,
                                              const float* __restrict__ eps,
                                              const float* __restrict__ sig,
                                              const float* __restrict__ val1,
                                              const float* __restrict__ val2,
                                              const float* __restrict__ nmm1,
                                              const float* __restrict__ nmm2,
                                              const float* __restrict__ W2,
                                              const float* __restrict__ b2,
                                              const float* __restrict__ vdwc){
    int bix = blockIdx.x;          // j tile 0..11
    int biy = blockIdx.y;          // i tile (global) 0..47
    int r0  = biy*16;              // global ligand row
    int b   = r0 / N1;
    int i1  = r0 % N1;
    int j0  = bix*32;
    __shared__ float s_p1[16][DD];
    __shared__ float s_p2[32][DD+1];
    __shared__ float s_w2[5][DD];
    __shared__ float s_b2v[5];
    __shared__ float s_red[16];
    int tid = threadIdx.x, lane = tid & 31, w = tid >> 5;
    int j  = lane;
    int ia = w*2;
    for (int idx = tid; idx < 5*DD; idx += 256) s_w2[idx/DD][idx%DD] = W2[idx];
    if (tid < 5) s_b2v[tid] = b2[tid];
    float acc[2][5];
    #pragma unroll
    for (int q = 0; q < 2; q++)
        #pragma unroll
        for (int m = 0; m < 5; m++) acc[q][m] = 0.f;
    for (int m = 0; m < 5; m++){
        __syncthreads();
        for (int idx = tid; idx < 16*DD; idx += 256)
            s_p1[idx/DD][idx%DD] = g_p1[(m*BB*N1 + r0 + idx/DD)*DD + idx%DD];
        for (int idx = tid; idx < 32*DD; idx += 256){
            int jj = idx/DD, hh = idx%DD;
            s_p2[jj][hh] = g_p2[(m*BB*N2 + b*N2 + j0 + jj)*DD + hh];
        }
        __syncthreads();
        float a0 = 0.f, a1 = 0.f;
        #pragma unroll 4
        for (int hh = 0; hh < DD; hh++){
            float wv  = s_w2[m][hh];
            float p2v = s_p2[j][hh];
            float pa  = s_p1[ia][hh];
            float pb  = s_p1[ia+1][hh];
            a0 = fmaf(fmaxf(pa + p2v, 0.f), wv, a0);
            a1 = fmaf(fmaxf(pb + p2v, 0.f), wv, a1);
        }
        acc[0][m] = a0; acc[1][m] = a1;
    }
    float vdwc2 = vdwc[0]*vdwc[0];
    float ec = 0.f, ev = 0.f;
    int jl = j0 + j;
    float c2v = c2[b*N2 + jl], v2v = val2[b*N2 + jl], n2v = nmm2[b*N2 + jl];
    #pragma unroll
    for (int q = 0; q < 2; q++){
        int il = i1 + ia + q;
        float v0 = acc[q][0] + s_b2v[0];
        float v1 = acc[q][1] + s_b2v[1];
        float v2 = acc[q][2] + s_b2v[2];
        float v3 = acc[q][3] + s_b2v[3];
        float v4 = acc[q][4] + s_b2v[4];
        int pix = (b*N1 + il)*N2 + jl;
        const float* dv = dmv + (size_t)pix*3;
        float dx = dv[0], dy = dv[1], dz = dv[2];
        float dm = sqrtf(dx*dx + dy*dy + dz*dz + 1e-10f);
        if (dm < 0.5f) dm = 1e10f;
        float l2dm = __log2f(dm);
        // coulomb
        float cA  = sigmoidf_(v0);
        float cN  = 2.f*sigmoidf_(v1) + 1.f;
        float q12 = c1[b*N1 + il]*c2v;
        float e_c = cA*q12*exp2f(-cN*l2dm);
        e_c *= val1[b*N1 + il]*v2v;
        e_c = fminf(fmaxf(e_c, -100.f), 100.f);
        // vdw
        float vAv = (0.6f*sigmoidf_(v2) + 0.7f)*vdwc2*eps[pix];
        float vBv = tanhf(v3)*0.6f + 0.7f;
        float vNv = 2.f*sigmoidf_(v4) + 5.f;
        float dm0 = sig[pix]*vBv;
        if (dm0 < 1e-4f) dm0 = 1.f;
        float r  = exp2f(vNv*(__log2f(dm0) - l2dm));
        float e_v = vAv*(r*r - 2.f*r);
        e_v *= nmm1[b*N1 + il]*n2v;
        e_v = fminf(e_v, 100.f);
        ec += e_c; ev += e_v;
    }
    #pragma unroll
    for (int o = 16; o; o >>= 1){
        ec += __shfl_xor_sync(0xffffffffu, ec, o);
        ev += __shfl_xor_sync(0xffffffffu, ev, o);
    }
    if (lane == 0){ s_red[w] = ec; s_red[8 + w] = ev; }
    __syncthreads();
    if (tid == 0){
        float tec = 0.f, tev = 0.f;
        #pragma unroll
        for (int qq = 0; qq < 8; qq++){ tec += s_red[qq]; tev += s_red[8 + qq]; }
        g_pec[biy*12 + bix] = tec;
        g_pev[biy*12 + bix] = tev;
    }
}

// ---------------- finalize ----------------
__global__ __launch_bounds__(DD) void k_final(const float* __restrict__ valid1,
                                              const float* __restrict__ delta_uff,
                                              const float* __restrict__ duff,
                                              const float* __restrict__ iW1,
                                              const float* __restrict__ ib1,
                                              const float* __restrict__ iW2,
                                              const float* __restrict__ ib2,
                                              float* __restrict__ out){
    int b = blockIdx.x, d = threadIdx.x;
    __shared__ float s_hs[DD];
    __shared__ float s_red[DD];
    float hs = 0.f;
    for (int i = 0; i < N1; i++) hs += g_h1g[(b*N1 + i)*DD + d]*valid1[b*N1 + i];
    s_hs[d] = hs;
    __syncthreads();
    float hid = ib1[d];
    #pragma unroll 4
    for (int k = 0; k < DD; k++) hid += s_hs[k]*iW1[k*HH + d];
    hid = fmaxf(hid, 0.f);
    s_red[d] = hid*iW2[d];
    __syncthreads();
    for (int s = 64; s; s >>= 1){ if (d < s) s_red[d] += s_red[d + s]; __syncthreads(); }
    if (d == 0){
        float inter = s_red[0] + ib2[0];
        float tec = 0.f, tev = 0.f;
        for (int q = 0; q < 288; q++){ tec += g_pec[b*288 + q]; tev += g_pev[b*288 + q]; }
        out[b*4 + 0] = tec;
        out[b*4 + 1] = tev;
        out[b*4 + 2] = duff[0]*duff[0]*delta_uff[b];
        out[b*4 + 3] = inter;
    }
}

// ---------------- launch ----------------
// d_in follows setup_inputs() dict insertion order:
//   0:h1 1:h2 2:adj1 3:dmv 4:charge1 5:charge2 6:vdw_epsilon 7:vdw_sigma
//   8:delta_uff 9:valid1 10:valid2 11:no_metal1 12:no_metal2 13:node_W
//   14:gat_W 15:gat_Wb 16:gat_A 17:gat_gW 18:gat_gb 19:pair_W1 20:pair_b1
//   21:pair_W2 22:pair_b2 23:vdw_coeff 24:duff_coeff 25:int_W1 26:int_b1
//   27:int_W2 28:int_b2
extern "C" void kernel_launch(void* const* d_in, const int* in_sizes, int n_in,
                              void* d_out, int out_size){
    const float* h1        = (const float*)d_in[0];
    const float* h2        = (const float*)d_in[1];
    const float* adj1      = (const float*)d_in[2];
    const float* dmv       = (const float*)d_in[3];
    const float* charge1   = (const float*)d_in[4];
    const float* charge2   = (const float*)d_in[5];
    const float* eps       = (const float*)d_in[6];
    const float* sig       = (const float*)d_in[7];
    const float* delta_uff = (const float*)d_in[8];
    const float* valid1    = (const float*)d_in[9];
    const float* valid2    = (const float*)d_in[10];
    const float* nm1       = (const float*)d_in[11];
    const float* nm2       = (const float*)d_in[12];
    const float* nodeW     = (const float*)d_in[13];
    const float* gatW      = (const float*)d_in[14];
    const float* gatWb     = (const float*)d_in[15];
    const float* gatA      = (const float*)d_in[16];
    const float* gatgW     = (const float*)d_in[17];
    const float* gatgb     = (const float*)d_in[18];
    const float* pW1       = (const float*)d_in[19];
    const float* pb1       = (const float*)d_in[20];
    const float* pW2       = (const float*)d_in[21];
    const float* pb2       = (const float*)d_in[22];
    const float* vdwc      = (const float*)d_in[23];
    const float* duffc     = (const float*)d_in[24];
    const float* iW1       = (const float*)d_in[25];
    const float* ib1       = (const float*)d_in[26];
    const float* iW2       = (const float*)d_in[27];
    const float* ib2       = (const float*)d_in[28];
    float* out = (float*)d_out;

    static int smem_set = 0;
    if (!smem_set){
        cudaFuncSetAttribute(k_soft, cudaFuncAttributeMaxDynamicSharedMemorySize, SOFT_SMEM);
        smem_set = 1;
    }

    k_precompute<<<LL*DD, DD>>>(gatW, gatWb, gatA);
    k_node<<<(BB*(N1 + N2))/4, DD>>>(h1, h2, nodeW);
    for (int l = 0; l < LL; l++){
        k_gat_h <<<BB*N1/16, DD>>>(gatW, gatWb, l);
        k_e     <<<dim3(N1/ET, N1/ET, BB), 256>>>();
        k_soft  <<<dim3(N1/32, BB), 256, SOFT_SMEM>>>(adj1);
        k_hprime<<<BB*N1/16, DD>>>(gatgW, gatgb, l);
    }
    {
        dim3 gp((BB*(N1 + N2))/16, 5);
        k_pairproj<<<gp, HH>>>(pW1, pb1);
    }
    k_pair<<<dim3(N2/32, BB*N1/16), 256>>>(dmv, charge1, charge2, eps, sig,
                                           valid1, valid2, nm1, nm2, pW2, pb2, vdwc);
    k_final<<<BB, DD>>>(valid1, delta_uff, duffc, iW1, ib1, iW2, ib2, out);
}

// round 4
// speedup vs baseline: 1.9154x; 1.2407x over previous
#include <cuda_runtime.h>
#include <math.h>

#define BB 2
#define N1 384
#define N2 384
#define DD 128
#define HH 128
#define LL 3
#define NF 54

// ---------------- scratch (device globals; no allocation) ----------------
static __device__ float g_h1g[BB*N1*DD];
static __device__ float g_h2g[BB*N2*DD];
static __device__ float g_hX [2*BB*N1*DD];   // ping-pong h
static __device__ float g_hAX[2*BB*N1*DD];   // ping-pong hA
static __device__ float g_P  [BB*N1*N1];
static __device__ float g_att[BB*N1*N1];
static __device__ float g_p1 [5*BB*N1*HH];
static __device__ float g_p2 [5*BB*N2*HH];
static __device__ float g_WA [LL*DD*DD];
static __device__ float g_bA [LL*DD];
static __device__ float g_pec[576];
static __device__ float g_pev[576];

__device__ __forceinline__ float sigmoidf_(float x){ return 1.f/(1.f+__expf(-x)); }

// ---------------- fused: WA=W@A, bA=Wb@A  +  node projection ----------------
__global__ __launch_bounds__(128) void k_pre_node(const float* __restrict__ W,
                                                  const float* __restrict__ Wb,
                                                  const float* __restrict__ A,
                                                  const float* __restrict__ h1,
                                                  const float* __restrict__ h2,
                                                  const float* __restrict__ nW){
    int bi = blockIdx.x, d = threadIdx.x;
    if (bi < LL*DD){
        int l = bi / DD, k = bi % DD;
        __shared__ float sw[DD];
        __shared__ float sb[DD];
        sw[d] = W[(l*DD + k)*DD + d];
        if (k == 0) sb[d] = Wb[l*DD + d];
        __syncthreads();
        const float* Al = A + l*DD*DD;
        float acc = 0.f;
        #pragma unroll 4
        for (int m = 0; m < DD; m++) acc += sw[m]*Al[m*DD + d];
        g_WA[(l*DD + k)*DD + d] = acc;
        if (k == 0){
            float bacc = 0.f;
            #pragma unroll 4
            for (int m = 0; m < DD; m++) bacc += sb[m]*Al[m*DD + d];
            g_bA[l*DD + d] = bacc;
        }
    } else {
        int r0 = (bi - LL*DD)*4;
        __shared__ float sx[4][NF];
        bool lig = (r0 < BB*N1);
        const float* src = lig ? (h1 + r0*NF) : (h2 + (r0 - BB*N1)*NF);
        for (int idx = d; idx < 4*NF; idx += 128) ((float*)sx)[idx] = src[idx];
        __syncthreads();
        float acc[4] = {0.f,0.f,0.f,0.f};
        #pragma unroll 2
        for (int k = 0; k < NF; k++){
            float wv = nW[k*DD + d];
            #pragma unroll
            for (int ii = 0; ii < 4; ii++) acc[ii] += sx[ii][k]*wv;
        }
        float* dst = lig ? (g_h1g + r0*DD) : (g_h2g + (r0 - BB*N1)*DD);
        #pragma unroll
        for (int ii = 0; ii < 4; ii++) dst[ii*DD + d] = acc[ii];
    }
}

// ---------------- stage2: gat_h layer0 (96 blocks) + protein pair-proj (240 blocks) ----------------
__global__ __launch_bounds__(128) void k_stage2(const float* __restrict__ gatW,
                                                const float* __restrict__ gatWb,
                                                const float* __restrict__ W1){
    int bi = blockIdx.x, d = threadIdx.x;
    __shared__ float sx[16][DD];
    if (bi < 96){
        int r0 = bi*8;
        #pragma unroll
        for (int ii = 0; ii < 8; ii++) sx[ii][d] = g_h1g[(r0 + ii)*DD + d];
        __syncthreads();
        const float* W  = gatW;
        const float* WA = g_WA;
        float wb  = gatWb[d];
        float bav = g_bA [d];
        float h[8], ha[8];
        #pragma unroll
        for (int ii = 0; ii < 8; ii++){ h[ii] = wb; ha[ii] = bav; }
        #pragma unroll 2
        for (int k = 0; k < DD; k++){
            float wv  = W [k*DD + d];
            float wav = WA[k*DD + d];
            #pragma unroll
            for (int ii = 0; ii < 8; ii++){
                h [ii] += sx[ii][k]*wv;
                ha[ii] += sx[ii][k]*wav;
            }
        }
        #pragma unroll
        for (int ii = 0; ii < 8; ii++){
            g_hX [(r0 + ii)*DD + d] = h [ii];
            g_hAX[(r0 + ii)*DD + d] = ha[ii];
        }
    } else {
        int pi = bi - 96;
        int m  = pi / 48;
        int r0 = (pi % 48)*16;
        #pragma unroll
        for (int ii = 0; ii < 16; ii++) sx[ii][d] = g_h2g[(r0 + ii)*DD + d];
        __syncthreads();
        const float* W = W1 + m*2*DD*HH + DD*HH;   // protein half, no bias
        float acc[16];
        #pragma unroll
        for (int ii = 0; ii < 16; ii++) acc[ii] = 0.f;
        #pragma unroll 2
        for (int k = 0; k < DD; k++){
            float wv = W[k*HH + d];
            #pragma unroll
            for (int ii = 0; ii < 16; ii++) acc[ii] = fmaf(sx[ii][k], wv, acc[ii]);
        }
        #pragma unroll
        for (int ii = 0; ii < 16; ii++) g_p2[(m*BB*N2 + r0 + ii)*HH + d] = acc[ii];
    }
}

// ---------------- P = hA @ h^T : 32x64 tiles, 144 blocks ----------------
__global__ __launch_bounds__(256) void k_e(int cur){
    const float* hb  = g_hX  + cur*BB*N1*DD;
    const float* hab = g_hAX + cur*BB*N1*DD;
    int b = blockIdx.z, j0 = blockIdx.y*32, k0 = blockIdx.x*64;
    __shared__ float sA[64][36];
    __shared__ float sB[64][68];
    int tid = threadIdx.x;
    int tx = tid & 15, ty = tid >> 4;
    float acc[2][4];
    #pragma unroll
    for (int r = 0; r < 2; r++)
        #pragma unroll
        for (int c = 0; c < 4; c++) acc[r][c] = 0.f;
    const float* baseA = hab + (b*N1 + j0)*DD;
    const float* baseB = hb  + (b*N1 + k0)*DD;
    for (int ks = 0; ks < 2; ks++){
        __syncthreads();
        #pragma unroll
        for (int q = 0; q < 2; q++){
            int idx = tid + q*256;
            int row = idx & 31, kq = idx >> 5;
            float4 va = *(const float4*)(baseA + row*DD + ks*64 + kq*4);
            sA[kq*4+0][row] = va.x; sA[kq*4+1][row] = va.y;
            sA[kq*4+2][row] = va.z; sA[kq*4+3][row] = va.w;
        }
        #pragma unroll
        for (int q = 0; q < 4; q++){
            int idx = tid + q*256;
            int row = idx & 63, kq = idx >> 6;
            float4 vb = *(const float4*)(baseB + row*DD + ks*64 + kq*4);
            sB[kq*4+0][row] = vb.x; sB[kq*4+1][row] = vb.y;
            sB[kq*4+2][row] = vb.z; sB[kq*4+3][row] = vb.w;
        }
        __syncthreads();
        #pragma unroll 8
        for (int kk = 0; kk < 64; kk++){
            float2 av = *(const float2*)&sA[kk][ty*2];
            float4 bv = *(const float4*)&sB[kk][tx*4];
            acc[0][0] = fmaf(av.x, bv.x, acc[0][0]);
            acc[0][1] = fmaf(av.x, bv.y, acc[0][1]);
            acc[0][2] = fmaf(av.x, bv.z, acc[0][2]);
            acc[0][3] = fmaf(av.x, bv.w, acc[0][3]);
            acc[1][0] = fmaf(av.y, bv.x, acc[1][0]);
            acc[1][1] = fmaf(av.y, bv.y, acc[1][1]);
            acc[1][2] = fmaf(av.y, bv.z, acc[1][2]);
            acc[1][3] = fmaf(av.y, bv.w, acc[1][3]);
        }
    }
    #pragma unroll
    for (int r = 0; r < 2; r++){
        float4 o = make_float4(acc[r][0], acc[r][1], acc[r][2], acc[r][3]);
        *(float4*)&g_P[(b*N1 + j0 + ty*2 + r)*N1 + k0 + tx*4] = o;
    }
}

// ---------------- column softmax of e = P + P^T, masked by adj (16 cols/block) ----------------
#define SOFT_SMEM ((N1*17 + 16*385)*4)
__global__ __launch_bounds__(256) void k_soft(const float* __restrict__ adj){
    extern __shared__ float sm[];
    float* sCol = sm;             // [384][17]
    float* sRow = sm + N1*17;     // [16][385]
    int b  = blockIdx.y;
    int c0 = blockIdx.x*16;
    int tid = threadIdx.x;
    for (int idx = tid; idx < N1*16; idx += 256){
        int r = idx >> 4, c = idx & 15;
        float p = g_P[(b*N1 + r)*N1 + c0 + c];
        float a = adj[(b*N1 + r)*N1 + c0 + c];
        sCol[r*17 + c] = (a > 0.f) ? p : -9e15f;
    }
    for (int idx = tid; idx < 16*N1; idx += 256){
        int cc = idx / N1, r = idx % N1;
        sRow[cc*385 + r] = g_P[(b*N1 + c0 + cc)*N1 + r];
    }
    __syncthreads();
    int w = tid >> 5, lane = tid & 31;
    for (int cc = w; cc < 16; cc += 8){
        float ev[12];
        float mx = -INFINITY;
        #pragma unroll
        for (int t = 0; t < 12; t++){
            int r = lane + t*32;
            float e = sCol[r*17 + cc];
            if (e > -8e15f) e += sRow[cc*385 + r];
            ev[t] = e;
            mx = fmaxf(mx, e);
        }
        #pragma unroll
        for (int o = 16; o; o >>= 1) mx = fmaxf(mx, __shfl_xor_sync(0xffffffffu, mx, o));
        float sum = 0.f;
        #pragma unroll
        for (int t = 0; t < 12; t++){
            float x = __expf(ev[t] - mx);
            ev[t] = x; sum += x;
        }
        #pragma unroll
        for (int o = 16; o; o >>= 1) sum += __shfl_xor_sync(0xffffffffu, sum, o);
        float inv = 1.f/sum;
        #pragma unroll
        for (int t = 0; t < 12; t++) sCol[(lane + t*32)*17 + cc] = ev[t]*inv;
    }
    __syncthreads();
    for (int idx = tid; idx < N1*16; idx += 256){
        int r = idx >> 4, c = idx & 15;
        float a = adj[(b*N1 + r)*N1 + c0 + c];
        g_att[(b*N1 + r)*N1 + c0 + c] = sCol[r*17 + c]*a;
    }
}

// ---------------- fused: h'=relu(att@h), gated residual, then next-layer h/hA ----------------
__global__ __launch_bounds__(128) void k_fuse(const float* __restrict__ gW,
                                              const float* __restrict__ gb,
                                              const float* __restrict__ gatW,
                                              const float* __restrict__ gatWb,
                                              int l, int has_next){
    int r0 = blockIdx.x*8;
    int b  = r0 / N1;
    int d  = threadIdx.x;
    const float* hb = g_hX + (l & 1)*BB*N1*DD;
    __shared__ float s_att[8][N1];
    __shared__ float s_g[8][DD];
    __shared__ float s_c[8];
    __shared__ float sx[8][DD];
    for (int idx = d; idx < 8*N1; idx += DD){
        int ii = idx / N1, j = idx % N1;
        s_att[ii][j] = g_att[(r0 + ii)*N1 + j];
    }
    float xd[8];
    #pragma unroll
    for (int ii = 0; ii < 8; ii++) xd[ii] = g_h1g[(r0 + ii)*DD + d];
    __syncthreads();
    float hp[8];
    #pragma unroll
    for (int ii = 0; ii < 8; ii++) hp[ii] = 0.f;
    const float* hcol = hb + (b*N1)*DD + d;
    #pragma unroll 4
    for (int j = 0; j < N1; j++){
        float hv = hcol[j*DD];
        #pragma unroll
        for (int ii = 0; ii < 8; ii++) hp[ii] = fmaf(s_att[ii][j], hv, hp[ii]);
    }
    float gw1 = gW[l*2*DD + d], gw2 = gW[l*2*DD + DD + d], gbv = gb[l];
    #pragma unroll
    for (int ii = 0; ii < 8; ii++){
        hp[ii] = fmaxf(hp[ii], 0.f);
        s_g[ii][d] = fmaf(xd[ii], gw1, hp[ii]*gw2);
    }
    __syncthreads();
    int w = d >> 5, lane = d & 31;
    for (int ii = w; ii < 8; ii += 4){
        float s = s_g[ii][lane] + s_g[ii][lane+32] + s_g[ii][lane+64] + s_g[ii][lane+96];
        #pragma unroll
        for (int o = 16; o; o >>= 1) s += __shfl_xor_sync(0xffffffffu, s, o);
        if (lane == 0) s_c[ii] = sigmoidf_(s + gbv);
    }
    __syncthreads();
    #pragma unroll
    for (int ii = 0; ii < 8; ii++){
        float coeff = s_c[ii];
        float v = coeff*xd[ii] + (1.f - coeff)*hp[ii];
        g_h1g[(r0 + ii)*DD + d] = v;
        sx[ii][d] = v;
    }
    if (!has_next) return;
    __syncthreads();
    int nl = l + 1;
    const float* W  = gatW + nl*DD*DD;
    const float* WA = g_WA + nl*DD*DD;
    float wb  = gatWb[nl*DD + d];
    float bav = g_bA [nl*DD + d];
    float h[8], ha[8];
    #pragma unroll
    for (int ii = 0; ii < 8; ii++){ h[ii] = wb; ha[ii] = bav; }
    #pragma unroll 2
    for (int k = 0; k < DD; k++){
        float wv  = W [k*DD + d];
        float wav = WA[k*DD + d];
        #pragma unroll
        for (int ii = 0; ii < 8; ii++){
            h [ii] += sx[ii][k]*wv;
            ha[ii] += sx[ii][k]*wav;
        }
    }
    float* ho  = g_hX  + (nl & 1)*BB*N1*DD;
    float* hao = g_hAX + (nl & 1)*BB*N1*DD;
    #pragma unroll
    for (int ii = 0; ii < 8; ii++){
        ho [(r0 + ii)*DD + d] = h [ii];
        hao[(r0 + ii)*DD + d] = ha[ii];
    }
}

// ---------------- ligand pair projections (16 rows/block, 240 blocks) ----------------
__global__ __launch_bounds__(128) void k_proj1(const float* __restrict__ W1,
                                               const float* __restrict__ b1){
    int bi = blockIdx.x;
    int m  = bi / 48;
    int r0 = (bi % 48)*16;
    int hh = threadIdx.x;
    __shared__ float sx[16][DD];
    #pragma unroll
    for (int ii = 0; ii < 16; ii++) sx[ii][hh] = g_h1g[(r0 + ii)*DD + hh];
    __syncthreads();
    const float* W = W1 + m*2*DD*HH;
    float bias = b1[m*HH + hh];
    float acc[16];
    #pragma unroll
    for (int ii = 0; ii < 16; ii++) acc[ii] = bias;
    #pragma unroll 2
    for (int k = 0; k < DD; k++){
        float wv = W[k*HH + hh];
        #pragma unroll
        for (int ii = 0; ii < 16; ii++) acc[ii] = fmaf(sx[ii][k], wv, acc[ii]);
    }
    #pragma unroll
    for (int ii = 0; ii < 16; ii++) g_p1[(m*BB*N1 + r0 + ii)*HH + hh] = acc[ii];
}

// ---------------- pair energies: 16i x 32j tile, float4 mainloop ----------------
__global__ __launch_bounds__(256) void k_pair(const float* __restrict__ dmv,
                                              const float* __restrict__ c1,
                                              const float* __restrict__ c2,
                                              const float* __restrict__ eps,
                                              const float* __restrict__ sig,
                                              const float* __restrict__ val1,
                                              const float* __restrict__ val2,
                                              const float* __restrict__ nmm1,
                                              const float* __restrict__ nmm2,
                                              const float* __restrict__ W2,
                                              const float* __restrict__ b2,
                                              const float* __restrict__ vdwc){
    int bix = blockIdx.x;          // j tile 0..11
    int biy = blockIdx.y;          // i tile 0..47
    int r0  = biy*16;
    int b   = r0 / N1;
    int i1  = r0 % N1;
    int j0  = bix*32;
    __shared__ float s_p1[16][132];
    __shared__ float s_p2[32][132];
    __shared__ float s_w2[5][128];
    __shared__ float s_b2v[5];
    __shared__ float s_red[16];
    int tid = threadIdx.x, lane = tid & 31, w = tid >> 5;
    int j  = lane;
    int ia = w*2;
    for (int idx = tid; idx < 5*DD; idx += 256) s_w2[idx/DD][idx%DD] = W2[idx];
    if (tid < 5) s_b2v[tid] = b2[tid];
    float acc[2][5];
    #pragma unroll
    for (int q = 0; q < 2; q++)
        #pragma unroll
        for (int m = 0; m < 5; m++) acc[q][m] = 0.f;
    for (int m = 0; m < 5; m++){
        __syncthreads();
        #pragma unroll
        for (int q = 0; q < 2; q++){
            int idx = tid + q*256;
            int row = idx >> 5, q4 = idx & 31;
            float4 v = *(const float4*)(g_p1 + (size_t)(m*BB*N1 + r0 + row)*HH + q4*4);
            *(float4*)&s_p1[row][q4*4] = v;
        }
        #pragma unroll
        for (int q = 0; q < 4; q++){
            int idx = tid + q*256;
            int row = idx >> 5, q4 = idx & 31;
            float4 v = *(const float4*)(g_p2 + (size_t)(m*BB*N2 + b*N2 + j0 + row)*HH + q4*4);
            *(float4*)&s_p2[row][q4*4] = v;
        }
        __syncthreads();
        float a0 = 0.f, a1 = 0.f;
        #pragma unroll
        for (int hv = 0; hv < 32; hv++){
            float4 w4  = *(const float4*)&s_w2[m][hv*4];
            float4 p2v = *(const float4*)&s_p2[j][hv*4];
            float4 pa  = *(const float4*)&s_p1[ia][hv*4];
            float4 pb  = *(const float4*)&s_p1[ia+1][hv*4];
            a0 = fmaf(fmaxf(pa.x + p2v.x, 0.f), w4.x, a0);
            a0 = fmaf(fmaxf(pa.y + p2v.y, 0.f), w4.y, a0);
            a0 = fmaf(fmaxf(pa.z + p2v.z, 0.f), w4.z, a0);
            a0 = fmaf(fmaxf(pa.w + p2v.w, 0.f), w4.w, a0);
            a1 = fmaf(fmaxf(pb.x + p2v.x, 0.f), w4.x, a1);
            a1 = fmaf(fmaxf(pb.y + p2v.y, 0.f), w4.y, a1);
            a1 = fmaf(fmaxf(pb.z + p2v.z, 0.f), w4.z, a1);
            a1 = fmaf(fmaxf(pb.w + p2v.w, 0.f), w4.w, a1);
        }
        acc[0][m] = a0; acc[1][m] = a1;
    }
    float vdwc2 = vdwc[0]*vdwc[0];
    float ec = 0.f, ev = 0.f;
    int jl = j0 + j;
    float c2v = c2[b*N2 + jl], v2v = val2[b*N2 + jl], n2v = nmm2[b*N2 + jl];
    #pragma unroll
    for (int q = 0; q < 2; q++){
        int il = i1 + ia + q;
        float v0 = acc[q][0] + s_b2v[0];
        float v1 = acc[q][1] + s_b2v[1];
        float v2 = acc[q][2] + s_b2v[2];
        float v3 = acc[q][3] + s_b2v[3];
        float v4 = acc[q][4] + s_b2v[4];
        int pix = (b*N1 + il)*N2 + jl;
        const float* dv = dmv + (size_t)pix*3;
        float dx = dv[0], dy = dv[1], dz = dv[2];
        float dm = sqrtf(dx*dx + dy*dy + dz*dz + 1e-10f);
        if (dm < 0.5f) dm = 1e10f;
        float l2dm = __log2f(dm);
        float cA  = sigmoidf_(v0);
        float cN  = 2.f*sigmoidf_(v1) + 1.f;
        float q12 = c1[b*N1 + il]*c2v;
        float e_c = cA*q12*exp2f(-cN*l2dm);
        e_c *= val1[b*N1 + il]*v2v;
        e_c = fminf(fmaxf(e_c, -100.f), 100.f);
        float vAv = (0.6f*sigmoidf_(v2) + 0.7f)*vdwc2*eps[pix];
        float vBv = tanhf(v3)*0.6f + 0.7f;
        float vNv = 2.f*sigmoidf_(v4) + 5.f;
        float dm0 = sig[pix]*vBv;
        if (dm0 < 1e-4f) dm0 = 1.f;
        float r  = exp2f(vNv*(__log2f(dm0) - l2dm));
        float e_v = vAv*(r*r - 2.f*r);
        e_v *= nmm1[b*N1 + il]*n2v;
        e_v = fminf(e_v, 100.f);
        ec += e_c; ev += e_v;
    }
    #pragma unroll
    for (int o = 16; o; o >>= 1){
        ec += __shfl_xor_sync(0xffffffffu, ec, o);
        ev += __shfl_xor_sync(0xffffffffu, ev, o);
    }
    if (lane == 0){ s_red[w] = ec; s_red[8 + w] = ev; }
    __syncthreads();
    if (tid == 0){
        float tec = 0.f, tev = 0.f;
        #pragma unroll
        for (int qq = 0; qq < 8; qq++){ tec += s_red[qq]; tev += s_red[8 + qq]; }
        g_pec[biy*12 + bix] = tec;
        g_pev[biy*12 + bix] = tev;
    }
}

// ---------------- finalize ----------------
__global__ __launch_bounds__(DD) void k_final(const float* __restrict__ valid1,
                                              const float* __restrict__ delta_uff,
                                              const float* __restrict__ duff,
                                              const float* __restrict__ iW1,
                                              const float* __restrict__ ib1,
                                              const float* __restrict__ iW2,
                                              const float* __restrict__ ib2,
                                              float* __restrict__ out){
    int b = blockIdx.x, d = threadIdx.x;
    __shared__ float s_hs[DD];
    __shared__ float s_red[DD];
    float hs = 0.f;
    for (int i = 0; i < N1; i++) hs += g_h1g[(b*N1 + i)*DD + d]*valid1[b*N1 + i];
    s_hs[d] = hs;
    __syncthreads();
    float hid = ib1[d];
    #pragma unroll 4
    for (int k = 0; k < DD; k++) hid += s_hs[k]*iW1[k*HH + d];
    hid = fmaxf(hid, 0.f);
    s_red[d] = hid*iW2[d];
    __syncthreads();
    for (int s = 64; s; s >>= 1){ if (d < s) s_red[d] += s_red[d + s]; __syncthreads(); }
    float inter = s_red[0] + ib2[0];
    __syncthreads();
    float tec = 0.f;
    for (int q = d; q < 288; q += DD) tec += g_pec[b*288 + q];
    s_red[d] = tec;
    __syncthreads();
    for (int s = 64; s; s >>= 1){ if (d < s) s_red[d] += s_red[d + s]; __syncthreads(); }
    float tecs = s_red[0];
    __syncthreads();
    float tev = 0.f;
    for (int q = d; q < 288; q += DD) tev += g_pev[b*288 + q];
    s_red[d] = tev;
    __syncthreads();
    for (int s = 64; s; s >>= 1){ if (d < s) s_red[d] += s_red[d + s]; __syncthreads(); }
    if (d == 0){
        out[b*4 + 0] = tecs;
        out[b*4 + 1] = s_red[0];
        out[b*4 + 2] = duff[0]*duff[0]*delta_uff[b];
        out[b*4 + 3] = inter;
    }
}

// ---------------- launch ----------------
// d_in follows setup_inputs() dict insertion order:
//   0:h1 1:h2 2:adj1 3:dmv 4:charge1 5:charge2 6:vdw_epsilon 7:vdw_sigma
//   8:delta_uff 9:valid1 10:valid2 11:no_metal1 12:no_metal2 13:node_W
//   14:gat_W 15:gat_Wb 16:gat_A 17:gat_gW 18:gat_gb 19:pair_W1 20:pair_b1
//   21:pair_W2 22:pair_b2 23:vdw_coeff 24:duff_coeff 25:int_W1 26:int_b1
//   27:int_W2 28:int_b2
extern "C" void kernel_launch(void* const* d_in, const int* in_sizes, int n_in,
                              void* d_out, int out_size){
    const float* h1        = (const float*)d_in[0];
    const float* h2        = (const float*)d_in[1];
    const float* adj1      = (const float*)d_in[2];
    const float* dmv       = (const float*)d_in[3];
    const float* charge1   = (const float*)d_in[4];
    const float* charge2   = (const float*)d_in[5];
    const float* eps       = (const float*)d_in[6];
    const float* sig       = (const float*)d_in[7];
    const float* delta_uff = (const float*)d_in[8];
    const float* valid1    = (const float*)d_in[9];
    const float* valid2    = (const float*)d_in[10];
    const float* nm1       = (const float*)d_in[11];
    const float* nm2       = (const float*)d_in[12];
    const float* nodeW     = (const float*)d_in[13];
    const float* gatW      = (const float*)d_in[14];
    const float* gatWb     = (const float*)d_in[15];
    const float* gatA      = (const float*)d_in[16];
    const float* gatgW     = (const float*)d_in[17];
    const float* gatgb     = (const float*)d_in[18];
    const float* pW1       = (const float*)d_in[19];
    const float* pb1       = (const float*)d_in[20];
    const float* pW2       = (const float*)d_in[21];
    const float* pb2       = (const float*)d_in[22];
    const float* vdwc      = (const float*)d_in[23];
    const float* duffc     = (const float*)d_in[24];
    const float* iW1       = (const float*)d_in[25];
    const float* ib1       = (const float*)d_in[26];
    const float* iW2       = (const float*)d_in[27];
    const float* ib2       = (const float*)d_in[28];
    float* out = (float*)d_out;

    static int attr_set = 0;
    if (!attr_set){
        cudaFuncSetAttribute(k_soft, cudaFuncAttributeMaxDynamicSharedMemorySize, SOFT_SMEM);
        attr_set = 1;
    }

    k_pre_node<<<LL*DD + (BB*(N1+N2))/4, 128>>>(gatW, gatWb, gatA, h1, h2, nodeW);
    k_stage2<<<96 + 240, 128>>>(gatW, gatWb, pW1);
    for (int l = 0; l < LL; l++){
        k_e   <<<dim3(N1/64, N1/32, BB), 256>>>(l & 1);
        k_soft<<<dim3(N1/16, BB), 256, SOFT_SMEM>>>(adj1);
        k_fuse<<<BB*N1/8, 128>>>(gatgW, gatgb, gatW, gatWb, l, (l < LL-1) ? 1 : 0);
    }
    k_proj1<<<240, 128>>>(pW1, pb1);
    k_pair<<<dim3(N2/32, BB*N1/16), 256>>>(dmv, charge1, charge2, eps, sig,
                                           valid1, valid2, nm1, nm2, pW2, pb2, vdwc);
    k_final<<<BB, DD>>>(valid1, delta_uff, duffc, iW1, ib1, iW2, ib2, out);
}